// round 4
// baseline (speedup 1.0000x reference)
#include <cuda_runtime.h>
#include <cuda_bf16.h>
#include <cfloat>
#include <cstdint>

// Problem constants
#define M_TOK   1024        // B*T = 8*128
#define KDIM    768         // hidden
#define VOC     21128       // vocab
#define MT      128
#define NT      128
#define KT      32
#define NTILES  166         // ceil(21128/128)
#define ASP     36          // As row pitch (floats), 144B-aligned rows
#define BSP     132         // Bs row pitch (floats), 528B-aligned rows

// Scratch (allocation-free): per-(token, n-tile) partial argmax
__device__ float g_pmax[(size_t)M_TOK * NTILES];
__device__ int   g_pidx[(size_t)M_TOK * NTILES];
__device__ int   g_mask_kind;   // 0=u8/bool bytes, 1=int32, 2=float32

// ---------------- f32x2 helpers (Blackwell packed FMA) ----------------
__device__ __forceinline__ unsigned long long ffma2(unsigned long long a,
                                                    unsigned long long b,
                                                    unsigned long long c) {
    unsigned long long d;
    asm("fma.rn.f32x2 %0, %1, %2, %3;" : "=l"(d) : "l"(a), "l"(b), "l"(c));
    return d;
}
__device__ __forceinline__ unsigned long long pack2(float lo, float hi) {
    unsigned long long p;
    asm("mov.b64 %0, {%1, %2};" : "=l"(p) : "f"(lo), "f"(hi));
    return p;
}
__device__ __forceinline__ float2 unpack2(unsigned long long p) {
    float lo, hi;
    asm("mov.b64 {%0, %1}, %2;" : "=f"(lo), "=f"(hi) : "l"(p));
    return make_float2(lo, hi);
}

// ---------------- mask dtype probe ----------------
// bool mask may arrive as 1-byte bool, int32(0/1), or float32(0.0/1.0).
// Inspect the first 21128 bytes (valid under every interpretation):
//   int32 0/1:  nonzero bytes only at pos%4==0
//   f32 0/1.0:  nonzero bytes (0x80,0x3F) only at pos%4 in {2,3}
//   u8 bool:    nonzero bytes at all residues
__global__ void probe_mask_kind(const unsigned char* __restrict__ mb) {
    __shared__ int nz[4];
    if (threadIdx.x < 4) nz[threadIdx.x] = 0;
    __syncthreads();
    for (int i = threadIdx.x; i < VOC; i += blockDim.x)
        if (mb[i]) atomicAdd(&nz[i & 3], 1);
    __syncthreads();
    if (threadIdx.x == 0) {
        int kind = 0;
        if (nz[0] > 0 && nz[1] == 0 && nz[2] == 0 && nz[3] == 0) kind = 1;
        else if (nz[0] == 0 && (nz[2] > 0 || nz[3] > 0))          kind = 2;
        g_mask_kind = kind;
    }
}

// ---------------- fused GEMM (+br +gumbel) -> per-tile argmax ----------------
// C[m,n] = sum_k A[m,k]*Wr[n,k]; tile 128x128, K-step 32, 256 threads,
// 8x8 microtile with f32x2 pairs over m.
__global__ __launch_bounds__(256, 2)
void gemm_argmax(const float* __restrict__ A,   // [1024,768]
                 const float* __restrict__ Wr,  // [21128,768]
                 const float* __restrict__ br,  // [21128]
                 const float* __restrict__ gum) // [1024,21128]
{
    __shared__ float As[MT * ASP];   // [m][k], row pitch 36
    __shared__ float Bs[KT * BSP];   // [k][n], row pitch 132 (transposed)

    const int tid = threadIdx.x;
    const int tx = tid & 15;         // n-direction (16)
    const int ty = tid >> 4;         // m-direction (16)
    const int bx = blockIdx.x;       // n-tile
    const int m0 = blockIdx.y * MT;
    const int n0 = bx * NT;

    unsigned long long acc[4][8];    // pairs over m (lo=even row), 8 n cols
    #pragma unroll
    for (int p = 0; p < 4; p++)
        #pragma unroll
        for (int j = 0; j < 8; j++) acc[p][j] = 0ULL;

    for (int kt = 0; kt < KDIM; kt += KT) {
        // Load A tile: 128x32, 4 float4 per thread, store [m][k]
        #pragma unroll
        for (int r = 0; r < 4; r++) {
            int lin = tid + r * 256;
            int mm = lin >> 3, kq = lin & 7;
            float4 v = *(const float4*)(A + (size_t)(m0 + mm) * KDIM + kt + kq * 4);
            *(float4*)(As + mm * ASP + kq * 4) = v;
        }
        // Load B tile: 128x32, transpose to [k][n]
        #pragma unroll
        for (int r = 0; r < 4; r++) {
            int lin = tid + r * 256;
            int nn = lin >> 3, kq = lin & 7;
            int row = n0 + nn;
            float4 v = make_float4(0.f, 0.f, 0.f, 0.f);
            if (row < VOC)
                v = *(const float4*)(Wr + (size_t)row * KDIM + kt + kq * 4);
            Bs[(kq * 4 + 0) * BSP + nn] = v.x;
            Bs[(kq * 4 + 1) * BSP + nn] = v.y;
            Bs[(kq * 4 + 2) * BSP + nn] = v.z;
            Bs[(kq * 4 + 3) * BSP + nn] = v.w;
        }
        __syncthreads();

        #pragma unroll 8
        for (int kk = 0; kk < KT; kk++) {
            float a[8];
            #pragma unroll
            for (int i = 0; i < 8; i++)
                a[i] = As[(ty * 8 + i) * ASP + kk];  // broadcast across tx
            unsigned long long a2[4];
            #pragma unroll
            for (int p = 0; p < 4; p++) a2[p] = pack2(a[2 * p], a[2 * p + 1]);

            float4 b0 = *(const float4*)(Bs + kk * BSP + tx * 8);
            float4 b1 = *(const float4*)(Bs + kk * BSP + tx * 8 + 4);
            unsigned long long bb[8];
            bb[0] = pack2(b0.x, b0.x); bb[1] = pack2(b0.y, b0.y);
            bb[2] = pack2(b0.z, b0.z); bb[3] = pack2(b0.w, b0.w);
            bb[4] = pack2(b1.x, b1.x); bb[5] = pack2(b1.y, b1.y);
            bb[6] = pack2(b1.z, b1.z); bb[7] = pack2(b1.w, b1.w);

            #pragma unroll
            for (int p = 0; p < 4; p++)
                #pragma unroll
                for (int j = 0; j < 8; j++)
                    acc[p][j] = ffma2(a2[p], bb[j], acc[p][j]);
        }
        __syncthreads();
    }

    // ---- Epilogue: +br +gumbel, argmax over this 128-wide n-tile ----
    const int nb = n0 + tx * 8;                     // VOC % 8 == 0 -> all-or-none
    float brv[8];
    if (nb < VOC) {
        float4 r0 = *(const float4*)(br + nb);
        float4 r1 = *(const float4*)(br + nb + 4);
        brv[0] = r0.x; brv[1] = r0.y; brv[2] = r0.z; brv[3] = r0.w;
        brv[4] = r1.x; brv[5] = r1.y; brv[6] = r1.z; brv[7] = r1.w;
    }

    #pragma unroll
    for (int i = 0; i < 8; i++) {
        const int gm = m0 + ty * 8 + i;
        float mx = -FLT_MAX;
        int   ai = 0x7fffffff;
        if (nb < VOC) {
            const float* gr = gum + (size_t)gm * VOC + nb;
            float4 g0 = *(const float4*)gr;
            float4 g1 = *(const float4*)(gr + 4);
            float gv[8] = {g0.x, g0.y, g0.z, g0.w, g1.x, g1.y, g1.z, g1.w};
            #pragma unroll
            for (int j = 0; j < 8; j++) {
                float2 u = unpack2(acc[i >> 1][j]);
                float v = ((i & 1) ? u.y : u.x) + brv[j] + gv[j];
                if (v > mx) { mx = v; ai = nb + j; }   // strict > keeps first idx
            }
        }
        // Warp butterfly over tx (lanes with same ty share m-rows)
        #pragma unroll
        for (int s = 1; s < 16; s <<= 1) {
            float omx = __shfl_xor_sync(0xffffffffu, mx, s);
            int   oai = __shfl_xor_sync(0xffffffffu, ai, s);
            if (omx > mx || (omx == mx && oai < ai)) { mx = omx; ai = oai; }
        }
        if (tx == 0) {
            g_pmax[(size_t)gm * NTILES + bx] = mx;
            g_pidx[(size_t)gm * NTILES + bx] = ai;
        }
    }
}

// ---------------- final reduce: per-token argmax over tiles, gather, loss ----
__global__ void reduce_loss(const float* __restrict__ sim,
                            const int* __restrict__ ids,
                            const void* __restrict__ mask,
                            float* __restrict__ out, int out_size)
{
    const int t = threadIdx.x;   // 1024 tokens, one block
    float mx = -FLT_MAX;
    int ai = 0;
    const float* pm = g_pmax + (size_t)t * NTILES;
    const int*   pi = g_pidx + (size_t)t * NTILES;
    for (int nt = 0; nt < NTILES; nt++) {
        float v = pm[nt];
        if (v > mx) { mx = v; ai = pi[nt]; }   // ascending tiles -> first max
    }
    const int id = ids[t];
    const int kind = g_mask_kind;
    bool ch;
    if (kind == 1)      ch = ((const int*)mask)[id] != 0;
    else if (kind == 2) ch = ((const float*)mask)[id] != 0.0f;
    else                ch = ((const unsigned char*)mask)[id] != 0;

    float contrib = ch ? (1.0f - sim[(size_t)id * VOC + ai]) : 0.0f;

    __shared__ float red[1024];
    red[t] = contrib;
    __syncthreads();
    for (int s = 512; s > 0; s >>= 1) {
        if (t < s) red[t] += red[t + s];
        __syncthreads();
    }
    if (t == 0) {
        float L = red[0] * (1.0f / 1024.0f);
        for (int k = 0; k < out_size; k++) out[k] = L;
    }
}

extern "C" void kernel_launch(void* const* d_in, const int* in_sizes, int n_in,
                              void* d_out, int out_size) {
    const float* seq  = (const float*)d_in[0];   // [8,128,768]
    const float* Wr   = (const float*)d_in[1];   // [21128,768]
    const float* br   = (const float*)d_in[2];   // [21128]
    const float* sim  = (const float*)d_in[3];   // [21128,21128]
    const float* gum  = (const float*)d_in[4];   // [8,128,21128]
    const int*   ids  = (const int*)d_in[5];     // [8,128]
    const void*  mask = d_in[6];                 // [21128] bool-ish

    probe_mask_kind<<<1, 256>>>((const unsigned char*)mask);

    dim3 grid(NTILES, M_TOK / MT);               // 166 x 8
    gemm_argmax<<<grid, 256>>>(seq, Wr, br, gum);

    reduce_loss<<<1, 1024>>>(sim, ids, mask, (float*)d_out, out_size);
}